// round 16
// baseline (speedup 1.0000x reference)
#include <cuda_runtime.h>
#include <cuda_fp16.h>
#include <cstdint>

// Problem constants
#define BB 4
#define SS 4096
#define DF 1024
#define HH 16
#define HD 64
#define SK 1024          // SS / STRIDE
#define STRIDE 4
#define BQ 128           // q rows per CTA
#define BK 64            // k cols per block
#define NBLK 16
#define NT 256
#define NQB 32           // q-blocks per (b,h)

// fp16 fragment-major scratch (packed half2 in uint) — layouts verified R14
// Kh: per (bh,kblk): [chunk(4)][ntile(8)][lane(32)] uint2  -> 8KB
// Vh: per (bh,kblk): [chunk(4)][dtile(8)][lane(32)] uint2  -> 8KB
// Qh: per (bh,qblk): [chunk(4)][warp(8)][lane(32)]  uint4  -> 16KB
__device__ uint2 g_kh[BB * HH * NBLK * 1024];
__device__ uint2 g_vh[BB * HH * NBLK * 1024];
__device__ uint4 g_qh[BB * HH * NQB * 1024];

// C += A * B, m16n8k16 fp16 inputs, fp32 accumulate
__device__ __forceinline__ void mma_f16(float c[4], uint32_t a0, uint32_t a1,
                                        uint32_t a2, uint32_t a3,
                                        uint32_t b0, uint32_t b1) {
    asm volatile(
        "mma.sync.aligned.m16n8k16.row.col.f32.f16.f16.f32 "
        "{%0,%1,%2,%3}, {%4,%5,%6,%7}, {%8,%9}, {%0,%1,%2,%3};"
        : "+f"(c[0]), "+f"(c[1]), "+f"(c[2]), "+f"(c[3])
        : "r"(a0), "r"(a1), "r"(a2), "r"(a3), "r"(b0), "r"(b1));
}
__device__ __forceinline__ uint32_t packh2(float a, float b) {
    __half2 h = __floats2half2_rn(a, b);
    return *reinterpret_cast<uint32_t*>(&h);
}
__device__ __forceinline__ float ex2f(float x) {
    float y;
    asm("ex2.approx.f32 %0, %1;" : "=f"(y) : "f"(x));
    return y;
}

// ---- merged pre-kernel: K/V (blocks 0..4095) and Q (blocks 4096..12287) ----
__global__ __launch_bounds__(NT)
void shuffle_all_kernel(const float* __restrict__ gq, const float* __restrict__ gk,
                        const float* __restrict__ gv)
{
    if (blockIdx.x < 4096) {
        // ---- K/V part (verbatim R14 shuffle_kvh) ----
        int id = blockIdx.x * NT + threadIdx.x;
        int lane = id & 31, t = (id >> 5) & 7, chunk = (id >> 8) & 3;
        int kblk = (id >> 10) & 15, bh = id >> 14;
        int gid = lane >> 2, gc = lane & 3;
        int bi = bh >> 4, hc = (bh & 15) * HD;
        size_t o = (size_t)(id >> 10) * 1024 + (chunk * 8 + t) * 32 + lane;
        {
            int srow = kblk * 64 + t * 8 + gid;
            const float* src = gk + ((size_t)bi * SS + (size_t)srow * STRIDE) * DF
                             + hc + chunk * 16 + 2 * gc;
            g_kh[o] = make_uint2(packh2(src[0], src[1]), packh2(src[8], src[9]));
        }
        {
            int key0 = kblk * 64 + chunk * 16 + 2 * gc;
            const float* src = gv + ((size_t)bi * SS + (size_t)key0 * STRIDE) * DF
                             + hc + t * 8 + gid;
            const size_t R = (size_t)STRIDE * DF;
            g_vh[o] = make_uint2(packh2(src[0], src[R]),
                                 packh2(src[8 * R], src[9 * R]));
        }
    } else {
        // ---- Q part (verbatim R14 shuffle_qh) ----
        const float SCL = 0.125f * 1.44269504088896341f;
        int id = (blockIdx.x - 4096) * NT + threadIdx.x;
        int lane = id & 31, warp = (id >> 5) & 7, chunk = (id >> 8) & 3;
        int qblk = (id >> 10) & 31, bh = id >> 15;
        int gid = lane >> 2, gc = lane & 3;
        int r = qblk * BQ + warp * 16 + gid;
        const float* src = gq + ((size_t)(bh >> 4) * SS + r) * DF
                         + (bh & 15) * HD + chunk * 16 + 2 * gc;
        const size_t R8 = (size_t)8 * DF;
        uint32_t a0 = packh2(src[0] * SCL,      src[1] * SCL);
        uint32_t a1 = packh2(src[R8] * SCL,     src[R8 + 1] * SCL);
        uint32_t a2 = packh2(src[8] * SCL,      src[9] * SCL);
        uint32_t a3 = packh2(src[R8 + 8] * SCL, src[R8 + 9] * SCL);
        g_qh[(size_t)(id >> 10) * 1024 + (chunk * 8 + warp) * 32 + lane] =
            make_uint4(a0, a1, a2, a3);
    }
}

// No smem, no barriers: fragments LDG'd directly (L1-cached, 8x reuse per CTA);
// warps fully independent (row sums are warp-local).
__global__ __launch_bounds__(NT, 2)
void attn_mma_kernel(float* __restrict__ out_a, float* __restrict__ out_w)
{
    const int tid = threadIdx.x, lane = tid & 31, warp = tid >> 5;
    const int gid = lane >> 2, gc = lane & 3;
    const int b = blockIdx.z, hh = blockIdx.y, qblk = blockIdx.x;
    const int bh = b * HH + hh;

    const uint2* __restrict__ kh = g_kh + (size_t)bh * NBLK * 1024;
    const uint2* __restrict__ vh = g_vh + (size_t)bh * NBLK * 1024;
    const uint4* __restrict__ qh = g_qh + ((size_t)bh * NQB + qblk) * 1024;

    // ---- Q fragments -> registers ----
    uint4 Qh[4];
    #pragma unroll
    for (int j = 0; j < 4; j++)
        Qh[j] = qh[(j * 8 + warp) * 32 + lane];

    float rs0 = 0.f, rs1 = 0.f;

    // ================= PASS 1: row sums (K via LDG, L1-cached) =================
    for (int blk = 0; blk < NBLK; blk++) {
        const uint2* kb = kh + blk * 1024 + lane;

        float S[8][4];
        #pragma unroll
        for (int t = 0; t < 8; t++) {
            S[t][0] = 0.f; S[t][1] = 0.f; S[t][2] = 0.f; S[t][3] = 0.f;
        }
        #pragma unroll
        for (int j = 0; j < 4; j++) {
            #pragma unroll
            for (int t = 0; t < 8; t++) {
                uint2 bk = kb[(j * 8 + t) * 32];
                mma_f16(S[t], Qh[j].x, Qh[j].y, Qh[j].z, Qh[j].w, bk.x, bk.y);
            }
        }
        #pragma unroll
        for (int t = 0; t < 8; t++) {
            rs0 += ex2f(S[t][0]) + ex2f(S[t][1]);
            rs1 += ex2f(S[t][2]) + ex2f(S[t][3]);
        }
    }

    // quad reduce (warp-local; all 4 lanes of each quad get totals)
    rs0 += __shfl_xor_sync(0xFFFFFFFFu, rs0, 1);
    rs0 += __shfl_xor_sync(0xFFFFFFFFu, rs0, 2);
    rs1 += __shfl_xor_sync(0xFFFFFFFFu, rs1, 1);
    rs1 += __shfl_xor_sync(0xFFFFFFFFu, rs1, 2);
    const float inv0 = 1.0f / rs0, inv1 = 1.0f / rs1;

    float Acc[8][4];
    #pragma unroll
    for (int t = 0; t < 8; t++) {
        Acc[t][0] = 0.f; Acc[t][1] = 0.f; Acc[t][2] = 0.f; Acc[t][3] = 0.f;
    }

    // ================= PASS 2: normalized w + PV (K/V via LDG) =================
    for (int blk = 0; blk < NBLK; blk++) {
        const uint2* kb = kh + blk * 1024 + lane;
        const uint2* vb = vh + blk * 1024 + lane;

        // ---- S = Q * K^T  (identical op order to pass 1 -> same bits) ----
        float S[8][4];
        #pragma unroll
        for (int t = 0; t < 8; t++) {
            S[t][0] = 0.f; S[t][1] = 0.f; S[t][2] = 0.f; S[t][3] = 0.f;
        }
        #pragma unroll
        for (int j = 0; j < 4; j++) {
            #pragma unroll
            for (int t = 0; t < 8; t++) {
                uint2 bk = kb[(j * 8 + t) * 32];
                mma_f16(S[t], Qh[j].x, Qh[j].y, Qh[j].z, Qh[j].w, bk.x, bk.y);
            }
        }

        // ---- normalized w -> gmem; P packed to fp16 a-frags ----
        float* wr0 = out_w + ((size_t)bh * SS + qblk * BQ + warp * 16 + gid) * SK
                   + blk * BK;
        float* wr1 = wr0 + (size_t)8 * SK;
        uint32_t Ph[8][2];
        #pragma unroll
        for (int t = 0; t < 8; t++) {
            float p0 = ex2f(S[t][0]) * inv0, p1 = ex2f(S[t][1]) * inv0;
            float p2 = ex2f(S[t][2]) * inv1, p3 = ex2f(S[t][3]) * inv1;
            int col = t * 8 + 2 * gc;
            *(float2*)&wr0[col] = make_float2(p0, p1);
            *(float2*)&wr1[col] = make_float2(p2, p3);
            Ph[t][0] = packh2(p0, p1);
            Ph[t][1] = packh2(p2, p3);
        }

        // ---- Acc += P * V  (chunk c uses P tiles 2c, 2c+1) ----
        #pragma unroll
        for (int c = 0; c < 4; c++) {
            #pragma unroll
            for (int t = 0; t < 8; t++) {
                uint2 bv = vb[(c * 8 + t) * 32];
                mma_f16(Acc[t], Ph[2 * c][0], Ph[2 * c][1],
                        Ph[2 * c + 1][0], Ph[2 * c + 1][1], bv.x, bv.y);
            }
        }
    }

    // ---- a: already normalized (P normalized before PV) ----
    {
        float* ar0 = out_a + ((size_t)(b * SS + qblk * BQ + warp * 16 + gid)) * DF
                   + hh * HD;
        float* ar1 = ar0 + (size_t)8 * DF;
        #pragma unroll
        for (int t = 0; t < 8; t++) {
            int col = t * 8 + 2 * gc;
            *(float2*)&ar0[col] = make_float2(Acc[t][0], Acc[t][1]);
            *(float2*)&ar1[col] = make_float2(Acc[t][2], Acc[t][3]);
        }
    }
}

extern "C" void kernel_launch(void* const* d_in, const int* in_sizes, int n_in,
                              void* d_out, int out_size)
{
    (void)in_sizes; (void)n_in; (void)out_size;
    const float* q = (const float*)d_in[0];
    const float* k = (const float*)d_in[1];
    const float* v = (const float*)d_in[2];

    float* out_a = (float*)d_out;
    float* out_w = out_a + (size_t)BB * SS * DF;  // w follows a

    shuffle_all_kernel<<<12288, NT>>>(q, k, v);

    dim3 grid(NQB, HH, BB);   // (32, 16, 4) = 2048 CTAs
    attn_mma_kernel<<<grid, NT>>>(out_a, out_w);
}